// round 1
// baseline (speedup 1.0000x reference)
#include <cuda_runtime.h>
#include <cuda_bf16.h>

#define BLK 128
#define NSWEEP 6

// index into upper-triangle storage, j<k, row-major over pairs:
// (0,1)..(0,7),(1,2)..(1,7),... matches Gell-Mann sym/antisym ordering.
__device__ __forceinline__ int uidx(int j, int k) {
    return j * 8 - (j * (j + 1)) / 2 + (k - j - 1);
}

__global__ __launch_bounds__(BLK)
void bes_kernel(const float* __restrict__ rho,
                const int* __restrict__ rank0p,
                const int* __restrict__ rank1p,
                float* __restrict__ out, int n)
{
    // staged input: 63 floats per thread, stride 65 for conflict-free LDS
    __shared__ float sv[BLK][65];
    const int tid = threadIdx.x;
    const int base = blockIdx.x * BLK;

    for (int i = tid; i < BLK * 63; i += BLK) {
        int t = i / 63, e = i - t * 63;
        if (base + t < n) sv[t][e] = rho[(long long)(base + t) * 63 + e];
    }
    __syncthreads();

    const int idx = base + tid;
    if (idx >= n) return;
    const float* v = sv[tid];

    // --- normalize ---
    float ss = 0.f;
#pragma unroll
    for (int i = 0; i < 63; ++i) ss += v[i] * v[i];
    const float inv = rsqrtf(ss);

    // --- diagonal of H = sum_i vec_i G_i (traceless; I/8 shift folded out) ---
    const float CL1 = 1.0f, CL2 = 0.57735026919f, CL3 = 0.40824829046f,
                CL4 = 0.31622776601f, CL5 = 0.25819888975f,
                CL6 = 0.21821789023f, CL7 = 0.18898223650f;
    float f[8];
    f[0] = 0.f;
    f[1] = CL1 * v[56] * inv; f[2] = CL2 * v[57] * inv; f[3] = CL3 * v[58] * inv;
    f[4] = CL4 * v[59] * inv; f[5] = CL5 * v[60] * inv; f[6] = CL6 * v[61] * inv;
    f[7] = CL7 * v[62] * inv;
    float dH[8];
    {
        float suf = 0.f;
#pragma unroll
        for (int j = 7; j >= 0; --j) {
            dH[j] = suf - (float)j * f[j];
            suf += f[j];
        }
    }

    const int n0 = 8 - rank0p[0];
    const int n1 = 8 - rank1p[0];

    float l0 = 0.f, l7 = 0.f;
    float sumS0 = 0.f, sumL0 = 0.f, sumS1 = 0.f, sumL1 = 0.f;
    float paMin = 0.f, paMax = 0.f, pcMin = 0.f, pcMax = 0.f;

    float  d8[8];
    float2 u[28];

    // mat 0: H   mat 1: PT_A(H)   mat 2: PT_C(H)
#pragma unroll 1
    for (int mat = 0; mat < 3; ++mat) {
        // ---- build upper triangle (pure index permutation of H) ----
#pragma unroll
        for (int j = 0; j < 8; ++j) {
#pragma unroll
            for (int k = j + 1; k < 8; ++k) {
                int r2, c2;
                if (mat == 0)      { r2 = j;                  c2 = k; }
                else if (mat == 1) { r2 = (j & 4) | (k & 3);  c2 = (k & 4) | (j & 3); }
                else               { r2 = (j & 6) | (k & 1);  c2 = (k & 6) | (j & 1); }
                int rr = r2 < c2 ? r2 : c2;
                int cc = r2 < c2 ? c2 : r2;
                int m2 = uidx(rr, cc);
                float re = v[m2] * inv;
                float im = v[28 + m2] * inv;      // H[rr][cc] = (re, -im)
                im = (r2 < c2) ? -im : im;        // conj if we need H[cc][rr]
                u[uidx(j, k)] = make_float2(re, im);
            }
        }
#pragma unroll
        for (int j = 0; j < 8; ++j) d8[j] = dH[j];  // PT preserves diagonal

        // ---- cyclic complex Hermitian Jacobi, fully unrolled pivots ----
#pragma unroll 1
        for (int sweep = 0; sweep < NSWEEP; ++sweep) {
#pragma unroll
            for (int p = 0; p < 8; ++p) {
#pragma unroll
                for (int q = p + 1; q < 8; ++q) {
                    float2 apq = u[uidx(p, q)];
                    float b2 = apq.x * apq.x + apq.y * apq.y;
                    bool ok = b2 > 1e-36f;
                    float binv = rsqrtf(ok ? b2 : 1.f);
                    float b  = ok ? b2 * binv : 0.f;       // |a_pq|
                    float er = ok ? apq.x * binv : 1.f;    // e^{-i phi}
                    float ei = ok ? -apq.y * binv : 0.f;
                    float th = (d8[p] - d8[q]) * 0.5f * binv;
                    float t  = copysignf(1.f / (fabsf(th) + sqrtf(th * th + 1.f)), th);
                    t = ok ? t : 0.f;                      // identity when b ~ 0
                    float c = rsqrtf(t * t + 1.f);
                    float s = t * c;
                    d8[p] += t * b;
                    d8[q] -= t * b;
                    u[uidx(p, q)] = make_float2(0.f, 0.f);
                    float swr = s * er, swi = s * ei;
                    float cwr = c * er, cwi = c * ei;
#pragma unroll
                    for (int k = 0; k < 8; ++k) {
                        if (k == p || k == q) continue;
                        float xr, xi, yr, yi;
                        if (k < p) { float2 tt = u[uidx(k, p)]; xr = tt.x; xi =  tt.y; }
                        else       { float2 tt = u[uidx(p, k)]; xr = tt.x; xi = -tt.y; }
                        if (k < q) { float2 tt = u[uidx(k, q)]; yr = tt.x; yi =  tt.y; }
                        else       { float2 tt = u[uidx(q, k)]; yr = tt.x; yi = -tt.y; }
                        // A[k][p] <- c*x + s*e^{-i phi}*y ; A[k][q] <- -s*x + c*e^{-i phi}*y
                        float nxr =  c * xr + swr * yr - swi * yi;
                        float nxi =  c * xi + swr * yi + swi * yr;
                        float nyr = -s * xr + cwr * yr - cwi * yi;
                        float nyi = -s * xi + cwr * yi + cwi * yr;
                        if (k < p) u[uidx(k, p)] = make_float2(nxr,  nxi);
                        else       u[uidx(p, k)] = make_float2(nxr, -nxi);
                        if (k < q) u[uidx(k, q)] = make_float2(nyr,  nyi);
                        else       u[uidx(q, k)] = make_float2(nyr, -nyi);
                    }
                }
            }
        }

        // ---- reduce eigenvalues ----
        if (mat == 0) {
            // bubble sorting network (28 CE), ascending
#pragma unroll
            for (int i = 0; i < 7; ++i)
#pragma unroll
                for (int j = 0; j < 7 - i; ++j) {
                    float lo = fminf(d8[j], d8[j + 1]);
                    float hi = fmaxf(d8[j], d8[j + 1]);
                    d8[j] = lo; d8[j + 1] = hi;
                }
            l0 = d8[0]; l7 = d8[7];
            sumS0 = sumL0 = sumS1 = sumL1 = 0.f;
#pragma unroll
            for (int i = 0; i < 8; ++i) {
                if (i < n0)      sumS0 += d8[i];
                if (i >= 8 - n0) sumL0 += d8[i];
                if (i < n1)      sumS1 += d8[i];
                if (i >= 8 - n1) sumL1 += d8[i];
            }
        } else {
            float mn = d8[0], mx = d8[0];
#pragma unroll
            for (int i = 1; i < 8; ++i) { mn = fminf(mn, d8[i]); mx = fmaxf(mx, d8[i]); }
            if (mat == 1) { paMin = mn; paMax = mx; }
            else          { pcMin = mn; pcMax = mx; }
        }
    }

    // eig(rho) = lam + 1/8 ; eig(dm_k) = beta_k*lam + 1/8 ; PT commutes with scale+shift
    const float beta0 = 1.f / (1.f - 8.f * (l0 + 0.125f));
    const float beta1 = 1.f / (1.f - 8.f * (l7 + 0.125f));

    float loss0 = beta0 * (beta0 >= 0.f ? sumS0 : sumL0) + (float)n0 * 0.125f;
    float loss1 = beta1 * (beta1 >= 0.f ? sumS1 : sumL1) + (float)n1 * 0.125f;
    float loss = (loss0 + loss1) * (loss0 + loss1);

    float lam;
    lam = beta0 * (beta0 >= 0.f ? paMin : paMax) + 0.125f; loss += lam * lam;
    lam = beta0 * (beta0 >= 0.f ? pcMin : pcMax) + 0.125f; loss += lam * lam;
    lam = beta1 * (beta1 >= 0.f ? paMin : paMax) + 0.125f; loss += lam * lam;
    lam = beta1 * (beta1 >= 0.f ? pcMin : pcMax) + 0.125f; loss += lam * lam;

    out[idx] = loss;
}

extern "C" void kernel_launch(void* const* d_in, const int* in_sizes, int n_in,
                              void* d_out, int out_size)
{
    const float* rho = (const float*)d_in[0];
    const int*   r0  = (const int*)d_in[1];
    const int*   r1  = (const int*)d_in[2];
    float* out = (float*)d_out;
    int n = in_sizes[0] / 63;
    int grid = (n + BLK - 1) / BLK;
    bes_kernel<<<grid, BLK>>>(rho, r0, r1, out, n);
}

// round 2
// speedup vs baseline: 1.2011x; 1.2011x over previous
#include <cuda_runtime.h>
#include <cuda_bf16.h>

#define EPB 32                 // elements per block
#define BLK (EPB * 3)          // 3 warps: warp w handles matrix w
#define NSWEEP 5

// upper-triangle index, j<k, matches Gell-Mann sym/antisym ordering
__device__ __forceinline__ int uidx(int j, int k) {
    return j * 8 - (j * (j + 1)) / 2 + (k - j - 1);
}

__global__ __launch_bounds__(BLK)
void bes_kernel(const float* __restrict__ rho,
                const int* __restrict__ rank0p,
                const int* __restrict__ rank1p,
                float* __restrict__ out, int n)
{
    __shared__ float sv[EPB][65];    // staged input, padded rows
    __shared__ float ex[EPB][4];     // paMin, paMax, pcMin, pcMax exchange

    const int tid  = threadIdx.x;
    const int mat  = tid >> 5;       // warp id = which matrix (0:H 1:PT_A 2:PT_C)
    const int e    = tid & 31;       // element within block
    const int base = blockIdx.x * EPB;

    // coalesced stage of 32*63 floats (2016 = 21 * 96)
    for (int i = tid; i < EPB * 63; i += BLK) {
        int t = i / 63, c = i - t * 63;
        if (base + t < n) sv[t][c] = rho[(long long)base * 63 + i];
    }
    __syncthreads();

    const float* v = sv[e];

    // --- normalize ---
    float ss = 0.f;
#pragma unroll
    for (int i = 0; i < 63; ++i) ss += v[i] * v[i];
    const float inv = rsqrtf(ss);

    // --- diagonal of H (traceless; I/8 folded out; PT preserves diagonal) ---
    const float CL1 = 1.0f, CL2 = 0.57735026919f, CL3 = 0.40824829046f,
                CL4 = 0.31622776601f, CL5 = 0.25819888975f,
                CL6 = 0.21821789023f, CL7 = 0.18898223650f;
    float f[8];
    f[0] = 0.f;
    f[1] = CL1 * v[56] * inv; f[2] = CL2 * v[57] * inv; f[3] = CL3 * v[58] * inv;
    f[4] = CL4 * v[59] * inv; f[5] = CL5 * v[60] * inv; f[6] = CL6 * v[61] * inv;
    f[7] = CL7 * v[62] * inv;
    float d8[8];
    {
        float suf = 0.f;
#pragma unroll
        for (int j = 7; j >= 0; --j) { d8[j] = suf - (float)j * f[j]; suf += f[j]; }
    }

    // --- build upper triangle: branchless PT permutation via bitmask select ---
    // r2 = (j & m) | (k & ~m), c2 = (k & m) | (j & ~m);  m: H=7, PT_A=4, PT_C=6
    const int m  = (mat == 0) ? 7 : (mat == 1 ? 4 : 6);
    const int mc = 7 ^ m;
    float2 u[28];
#pragma unroll
    for (int j = 0; j < 8; ++j) {
#pragma unroll
        for (int k = j + 1; k < 8; ++k) {
            int r2 = (j & m) | (k & mc);
            int c2 = (k & m) | (j & mc);
            int rr = r2 < c2 ? r2 : c2;
            int cc = r2 < c2 ? c2 : r2;
            int m2 = uidx(rr, cc);
            float re = v[m2] * inv;
            float im = v[28 + m2] * inv;
            im = (r2 < c2) ? -im : im;     // conj select
            u[uidx(j, k)] = make_float2(re, im);
        }
    }

    // --- cyclic complex Hermitian Jacobi, fully unrolled pivots ---
#pragma unroll 1
    for (int sweep = 0; sweep < NSWEEP; ++sweep) {
#pragma unroll
        for (int p = 0; p < 8; ++p) {
#pragma unroll
            for (int q = p + 1; q < 8; ++q) {
                float2 apq = u[uidx(p, q)];
                float b2 = apq.x * apq.x + apq.y * apq.y;
                bool ok = b2 > 1e-36f;
                float binv = rsqrtf(ok ? b2 : 1.f);
                float b  = ok ? b2 * binv : 0.f;       // |a_pq|
                float er = ok ? apq.x * binv : 1.f;    // e^{-i phi}
                float ei = ok ? -apq.y * binv : 0.f;
                float th = (d8[p] - d8[q]) * 0.5f * binv;
                float t  = copysignf(1.f / (fabsf(th) + sqrtf(th * th + 1.f)), th);
                t = ok ? t : 0.f;
                float c = rsqrtf(t * t + 1.f);
                float s = t * c;
                d8[p] += t * b;
                d8[q] -= t * b;
                u[uidx(p, q)] = make_float2(0.f, 0.f);
                float swr = s * er, swi = s * ei;
                float cwr = c * er, cwi = c * ei;
#pragma unroll
                for (int k = 0; k < 8; ++k) {
                    if (k == p || k == q) continue;
                    float xr, xi, yr, yi;
                    if (k < p) { float2 tt = u[uidx(k, p)]; xr = tt.x; xi =  tt.y; }
                    else       { float2 tt = u[uidx(p, k)]; xr = tt.x; xi = -tt.y; }
                    if (k < q) { float2 tt = u[uidx(k, q)]; yr = tt.x; yi =  tt.y; }
                    else       { float2 tt = u[uidx(q, k)]; yr = tt.x; yi = -tt.y; }
                    float nxr =  c * xr + swr * yr - swi * yi;
                    float nxi =  c * xi + swr * yi + swi * yr;
                    float nyr = -s * xr + cwr * yr - cwi * yi;
                    float nyi = -s * xi + cwr * yi + cwi * yr;
                    if (k < p) u[uidx(k, p)] = make_float2(nxr,  nxi);
                    else       u[uidx(p, k)] = make_float2(nxr, -nxi);
                    if (k < q) u[uidx(k, q)] = make_float2(nyr,  nyi);
                    else       u[uidx(q, k)] = make_float2(nyr, -nyi);
                }
            }
        }
    }

    // --- reduce (warp-uniform branch on mat) ---
    float l0 = 0.f, l7 = 0.f, sumS0 = 0.f, sumL0 = 0.f, sumS1 = 0.f, sumL1 = 0.f;
    int n0 = 0, n1 = 0;
    if (mat == 0) {
        // bubble sorting network, ascending
#pragma unroll
        for (int i = 0; i < 7; ++i)
#pragma unroll
            for (int j = 0; j < 7 - i; ++j) {
                float lo = fminf(d8[j], d8[j + 1]);
                float hi = fmaxf(d8[j], d8[j + 1]);
                d8[j] = lo; d8[j + 1] = hi;
            }
        l0 = d8[0]; l7 = d8[7];
        n0 = 8 - rank0p[0];
        n1 = 8 - rank1p[0];
#pragma unroll
        for (int i = 0; i < 8; ++i) {
            if (i < n0)      sumS0 += d8[i];
            if (i >= 8 - n0) sumL0 += d8[i];
            if (i < n1)      sumS1 += d8[i];
            if (i >= 8 - n1) sumL1 += d8[i];
        }
    } else {
        float mn = d8[0], mx = d8[0];
#pragma unroll
        for (int i = 1; i < 8; ++i) { mn = fminf(mn, d8[i]); mx = fmaxf(mx, d8[i]); }
        ex[e][(mat - 1) * 2 + 0] = mn;
        ex[e][(mat - 1) * 2 + 1] = mx;
    }
    __syncthreads();

    if (mat == 0 && base + e < n) {
        float paMin = ex[e][0], paMax = ex[e][1];
        float pcMin = ex[e][2], pcMax = ex[e][3];

        const float beta0 = 1.f / (1.f - 8.f * (l0 + 0.125f));
        const float beta1 = 1.f / (1.f - 8.f * (l7 + 0.125f));

        float loss0 = beta0 * (beta0 >= 0.f ? sumS0 : sumL0) + (float)n0 * 0.125f;
        float loss1 = beta1 * (beta1 >= 0.f ? sumS1 : sumL1) + (float)n1 * 0.125f;
        float loss = (loss0 + loss1) * (loss0 + loss1);

        float lam;
        lam = beta0 * (beta0 >= 0.f ? paMin : paMax) + 0.125f; loss += lam * lam;
        lam = beta0 * (beta0 >= 0.f ? pcMin : pcMax) + 0.125f; loss += lam * lam;
        lam = beta1 * (beta1 >= 0.f ? paMin : paMax) + 0.125f; loss += lam * lam;
        lam = beta1 * (beta1 >= 0.f ? pcMin : pcMax) + 0.125f; loss += lam * lam;

        out[base + e] = loss;
    }
}

extern "C" void kernel_launch(void* const* d_in, const int* in_sizes, int n_in,
                              void* d_out, int out_size)
{
    const float* rho = (const float*)d_in[0];
    const int*   r0  = (const int*)d_in[1];
    const int*   r1  = (const int*)d_in[2];
    float* out = (float*)d_out;
    int n = in_sizes[0] / 63;
    int grid = (n + EPB - 1) / EPB;
    bes_kernel<<<grid, BLK>>>(rho, r0, r1, out, n);
}

// round 5
// speedup vs baseline: 1.4024x; 1.1676x over previous
#include <cuda_runtime.h>
#include <cuda_bf16.h>

#define EPB 32                 // elements per block
#define BLK (EPB * 3)          // 3 warps: warp w handles matrix w
#define NSWEEP 4

// upper-triangle index, j<k, matches Gell-Mann sym/antisym ordering
__device__ __forceinline__ int uidx(int j, int k) {
    return j * 8 - (j * (j + 1)) / 2 + (k - j - 1);
}

__global__ __launch_bounds__(BLK)
void bes_kernel(const float* __restrict__ rho,
                const int* __restrict__ rank0p,
                const int* __restrict__ rank1p,
                float* __restrict__ out, int n)
{
    // round-robin tournament: 7 rounds x 4 disjoint pairs = all 28 pairs.
    // function-local constexpr: folded to immediates under full unrolling.
    constexpr int PAIRS[7][4][2] = {
        {{0,7},{1,6},{2,5},{3,4}},
        {{0,4},{1,7},{2,6},{3,5}},
        {{0,1},{2,7},{3,6},{4,5}},
        {{0,5},{1,2},{3,7},{4,6}},
        {{0,2},{1,3},{4,7},{5,6}},
        {{0,6},{1,4},{2,3},{5,7}},
        {{0,3},{1,5},{2,4},{6,7}},
    };

    __shared__ float sv[EPB][65];    // staged input, padded rows
    __shared__ float ex[EPB][4];     // paMin, paMax, pcMin, pcMax exchange

    const int tid  = threadIdx.x;
    const int mat  = tid >> 5;       // warp id = matrix (0:H 1:PT_A 2:PT_C)
    const int e    = tid & 31;
    const int base = blockIdx.x * EPB;

    // hoist tiny scalar loads so their latency hides under the Jacobi body
    const int n0 = 8 - rank0p[0];
    const int n1 = 8 - rank1p[0];

    for (int i = tid; i < EPB * 63; i += BLK) {
        int t = i / 63;
        if (base + t < n) sv[t][i - t * 63] = rho[(long long)base * 63 + i];
    }
    __syncthreads();

    const float* v = sv[e];

    // --- normalize ---
    float ss = 0.f;
#pragma unroll
    for (int i = 0; i < 63; ++i) ss += v[i] * v[i];
    const float inv = rsqrtf(ss);

    // --- diagonal of H (traceless; I/8 folded out; PT preserves diagonal) ---
    const float CL1 = 1.0f, CL2 = 0.57735026919f, CL3 = 0.40824829046f,
                CL4 = 0.31622776601f, CL5 = 0.25819888975f,
                CL6 = 0.21821789023f, CL7 = 0.18898223650f;
    float f[8];
    f[0] = 0.f;
    f[1] = CL1 * v[56] * inv; f[2] = CL2 * v[57] * inv; f[3] = CL3 * v[58] * inv;
    f[4] = CL4 * v[59] * inv; f[5] = CL5 * v[60] * inv; f[6] = CL6 * v[61] * inv;
    f[7] = CL7 * v[62] * inv;
    float d8[8];
    {
        float suf = 0.f;
#pragma unroll
        for (int j = 7; j >= 0; --j) { d8[j] = suf - (float)j * f[j]; suf += f[j]; }
    }

    // --- build upper triangle: branchless PT permutation via bitmask select ---
    const int m  = (mat == 0) ? 7 : (mat == 1 ? 4 : 6);
    const int mc = 7 ^ m;
    float2 u[28];
#pragma unroll
    for (int j = 0; j < 8; ++j) {
#pragma unroll
        for (int k = j + 1; k < 8; ++k) {
            int r2 = (j & m) | (k & mc);
            int c2 = (k & m) | (j & mc);
            int rr = r2 < c2 ? r2 : c2;
            int cc = r2 < c2 ? c2 : r2;
            int m2 = uidx(rr, cc);
            float re = v[m2] * inv;
            float im = v[28 + m2] * inv;
            im = (r2 < c2) ? -im : im;
            u[uidx(j, k)] = make_float2(re, im);
        }
    }

    // --- parallel-ordering complex Hermitian Jacobi ---
    // Each round: 4 disjoint pairs; param chains computed together (4-way ILP),
    // updates applied sequentially (== sequential application: disjoint pairs
    // never touch each other's pivot entries or diagonals).
#pragma unroll 1
    for (int sweep = 0; sweep < NSWEEP; ++sweep) {
#pragma unroll
        for (int r = 0; r < 7; ++r) {
            float cc4[4], ss4[4], wr4[4], wi4[4];
#pragma unroll
            for (int a = 0; a < 4; ++a) {
                const int p = PAIRS[r][a][0], q = PAIRS[r][a][1];
                float2 apq = u[uidx(p, q)];
                float b2 = apq.x * apq.x + apq.y * apq.y;
                bool ok = b2 > 1e-36f;
                float binv = rsqrtf(ok ? b2 : 1.f);
                float b  = ok ? b2 * binv : 0.f;       // |a_pq|
                float er = ok ? apq.x * binv : 1.f;    // e^{-i phi}
                float ei = ok ? -apq.y * binv : 0.f;
                float th = (d8[p] - d8[q]) * 0.5f * binv;
                float t  = copysignf(1.f / (fabsf(th) + sqrtf(th * th + 1.f)), th);
                t = ok ? t : 0.f;
                float c = rsqrtf(t * t + 1.f);
                float s = t * c;
                d8[p] += t * b;
                d8[q] -= t * b;
                u[uidx(p, q)] = make_float2(0.f, 0.f);
                cc4[a] = c; ss4[a] = s; wr4[a] = er; wi4[a] = ei;
            }
#pragma unroll
            for (int a = 0; a < 4; ++a) {
                const int p = PAIRS[r][a][0], q = PAIRS[r][a][1];
                const float c = cc4[a], s = ss4[a];
                const float swr = s * wr4[a], swi = s * wi4[a];
                const float cwr = c * wr4[a], cwi = c * wi4[a];
#pragma unroll
                for (int k = 0; k < 8; ++k) {
                    if (k == p || k == q) continue;
                    float xr, xi, yr, yi;
                    if (k < p) { float2 tt = u[uidx(k, p)]; xr = tt.x; xi =  tt.y; }
                    else       { float2 tt = u[uidx(p, k)]; xr = tt.x; xi = -tt.y; }
                    if (k < q) { float2 tt = u[uidx(k, q)]; yr = tt.x; yi =  tt.y; }
                    else       { float2 tt = u[uidx(q, k)]; yr = tt.x; yi = -tt.y; }
                    float nxr =  c * xr + swr * yr - swi * yi;
                    float nxi =  c * xi + swr * yi + swi * yr;
                    float nyr = -s * xr + cwr * yr - cwi * yi;
                    float nyi = -s * xi + cwr * yi + cwi * yr;
                    if (k < p) u[uidx(k, p)] = make_float2(nxr,  nxi);
                    else       u[uidx(p, k)] = make_float2(nxr, -nxi);
                    if (k < q) u[uidx(k, q)] = make_float2(nyr,  nyi);
                    else       u[uidx(q, k)] = make_float2(nyr, -nyi);
                }
            }
        }
    }

    // --- reduce (warp-uniform branch on mat) ---
    float l0 = 0.f, l7 = 0.f, sumS0 = 0.f, sumL0 = 0.f, sumS1 = 0.f, sumL1 = 0.f;
    if (mat == 0) {
#pragma unroll
        for (int i = 0; i < 7; ++i)
#pragma unroll
            for (int j = 0; j < 7 - i; ++j) {
                float lo = fminf(d8[j], d8[j + 1]);
                float hi = fmaxf(d8[j], d8[j + 1]);
                d8[j] = lo; d8[j + 1] = hi;
            }
        l0 = d8[0]; l7 = d8[7];
#pragma unroll
        for (int i = 0; i < 8; ++i) {
            if (i < n0)      sumS0 += d8[i];
            if (i >= 8 - n0) sumL0 += d8[i];
            if (i < n1)      sumS1 += d8[i];
            if (i >= 8 - n1) sumL1 += d8[i];
        }
    } else {
        float mn = d8[0], mx = d8[0];
#pragma unroll
        for (int i = 1; i < 8; ++i) { mn = fminf(mn, d8[i]); mx = fmaxf(mx, d8[i]); }
        ex[e][(mat - 1) * 2 + 0] = mn;
        ex[e][(mat - 1) * 2 + 1] = mx;
    }
    __syncthreads();

    if (mat == 0 && base + e < n) {
        float paMin = ex[e][0], paMax = ex[e][1];
        float pcMin = ex[e][2], pcMax = ex[e][3];

        const float beta0 = 1.f / (1.f - 8.f * (l0 + 0.125f));
        const float beta1 = 1.f / (1.f - 8.f * (l7 + 0.125f));

        float loss0 = beta0 * (beta0 >= 0.f ? sumS0 : sumL0) + (float)n0 * 0.125f;
        float loss1 = beta1 * (beta1 >= 0.f ? sumS1 : sumL1) + (float)n1 * 0.125f;
        float loss = (loss0 + loss1) * (loss0 + loss1);

        float lam;
        lam = beta0 * (beta0 >= 0.f ? paMin : paMax) + 0.125f; loss += lam * lam;
        lam = beta0 * (beta0 >= 0.f ? pcMin : pcMax) + 0.125f; loss += lam * lam;
        lam = beta1 * (beta1 >= 0.f ? paMin : paMax) + 0.125f; loss += lam * lam;
        lam = beta1 * (beta1 >= 0.f ? pcMin : pcMax) + 0.125f; loss += lam * lam;

        out[base + e] = loss;
    }
}

extern "C" void kernel_launch(void* const* d_in, const int* in_sizes, int n_in,
                              void* d_out, int out_size)
{
    const float* rho = (const float*)d_in[0];
    const int*   r0  = (const int*)d_in[1];
    const int*   r1  = (const int*)d_in[2];
    float* out = (float*)d_out;
    int n = in_sizes[0] / 63;
    int grid = (n + EPB - 1) / EPB;
    bes_kernel<<<grid, BLK>>>(rho, r0, r1, out, n);
}

// round 7
// speedup vs baseline: 1.9046x; 1.3581x over previous
#include <cuda_runtime.h>
#include <cuda_bf16.h>

#define EPB 32                 // elements per block
#define BLK (EPB * 3)          // 3 warps: warp w handles matrix w
#define NSWEEP 4

// upper-triangle index, j<k, matches Gell-Mann sym/antisym ordering
__device__ __forceinline__ int uidx(int j, int k) {
    return j * 8 - (j * (j + 1)) / 2 + (k - j - 1);
}

__global__ __launch_bounds__(BLK)
void bes_kernel(const float* __restrict__ rho,
                const int* __restrict__ rank0p,
                const int* __restrict__ rank1p,
                float* __restrict__ out, int n)
{
    __shared__ float sv[EPB][65];    // staged input, padded rows
    __shared__ float ex[EPB][4];     // paMin, paMax, pcMin, pcMax exchange

    const int tid  = threadIdx.x;
    const int mat  = tid >> 5;       // warp id = matrix (0:H 1:PT_A 2:PT_C)
    const int e    = tid & 31;
    const int base = blockIdx.x * EPB;

    // hoist tiny scalar loads so their latency hides under the Jacobi body
    const int n0 = 8 - rank0p[0];
    const int n1 = 8 - rank1p[0];

    for (int i = tid; i < EPB * 63; i += BLK) {
        int t = i / 63;
        if (base + t < n) sv[t][i - t * 63] = rho[(long long)base * 63 + i];
    }
    __syncthreads();

    const float* v = sv[e];

    // --- normalize ---
    float ss = 0.f;
#pragma unroll
    for (int i = 0; i < 63; ++i) ss += v[i] * v[i];
    const float inv = rsqrtf(ss);

    // --- diagonal of H (traceless; I/8 folded out; PT preserves diagonal) ---
    const float CL1 = 1.0f, CL2 = 0.57735026919f, CL3 = 0.40824829046f,
                CL4 = 0.31622776601f, CL5 = 0.25819888975f,
                CL6 = 0.21821789023f, CL7 = 0.18898223650f;
    float f[8];
    f[0] = 0.f;
    f[1] = CL1 * v[56] * inv; f[2] = CL2 * v[57] * inv; f[3] = CL3 * v[58] * inv;
    f[4] = CL4 * v[59] * inv; f[5] = CL5 * v[60] * inv; f[6] = CL6 * v[61] * inv;
    f[7] = CL7 * v[62] * inv;
    float d8[8];
    {
        float suf = 0.f;
#pragma unroll
        for (int j = 7; j >= 0; --j) { d8[j] = suf - (float)j * f[j]; suf += f[j]; }
    }

    // --- build upper triangle: branchless PT permutation via bitmask select ---
    const int m  = (mat == 0) ? 7 : (mat == 1 ? 4 : 6);
    const int mc = 7 ^ m;
    float2 u[28];
#pragma unroll
    for (int j = 0; j < 8; ++j) {
#pragma unroll
        for (int k = j + 1; k < 8; ++k) {
            int r2 = (j & m) | (k & mc);
            int c2 = (k & m) | (j & mc);
            int rr = r2 < c2 ? r2 : c2;
            int cc = r2 < c2 ? c2 : r2;
            int m2 = uidx(rr, cc);
            float re = v[m2] * inv;
            float im = v[28 + m2] * inv;
            im = (r2 < c2) ? -im : im;
            u[uidx(j, k)] = make_float2(re, im);
        }
    }

    // --- cyclic complex Hermitian Jacobi, direct-eigenvector rotation ---
    // 2x2 pivot [[dp, a],[conj(a), dq]] with a = u[uidx(p,q)]:
    //   v = sqrt(delta^2+|a|^2), sv = copysign(v, delta), u0 = delta + sv
    //   eigvec x = (u0, conj(a)) exactly satisfies (A - (m+sv) I) x = 0
    //   c = u0*ninv (real), w = conj(a)*ninv, ninv = rsqrt(u0^2+|a|^2)
    // Small-angle branch (c^2 >= 1/2), identical convergence to classic form;
    // 2 MUFU per rotation instead of 3, exact diagonal update m +/- sv.
#pragma unroll 1
    for (int sweep = 0; sweep < NSWEEP; ++sweep) {
#pragma unroll
        for (int p = 0; p < 8; ++p) {
#pragma unroll
            for (int q = p + 1; q < 8; ++q) {
                float2 apq = u[uidx(p, q)];
                float b2 = apq.x * apq.x + apq.y * apq.y;
                float dp = d8[p], dq = d8[q];
                float delta = (dp - dq) * 0.5f;
                float mm    = (dp + dq) * 0.5f;
                float v2 = fmaf(delta, delta, b2);
                bool ok = v2 > 1e-36f;
                float vv = sqrtf(v2);
                float sv2 = copysignf(vv, delta);
                float u0 = delta + sv2;
                float n2 = fmaf(u0, u0, b2);
                float ninv = rsqrtf(ok ? n2 : 1.f);
                float c  = ok ? u0 * ninv : 1.f;
                float wr = ok ? apq.x * ninv : 0.f;
                float wi = ok ? -apq.y * ninv : 0.f;
                d8[p] = mm + sv2;
                d8[q] = mm - sv2;
                u[uidx(p, q)] = make_float2(0.f, 0.f);
#pragma unroll
                for (int k = 0; k < 8; ++k) {
                    if (k == p || k == q) continue;
                    float xr, xi, yr, yi;
                    if (k < p) { float2 tt = u[uidx(k, p)]; xr = tt.x; xi =  tt.y; }
                    else       { float2 tt = u[uidx(p, k)]; xr = tt.x; xi = -tt.y; }
                    if (k < q) { float2 tt = u[uidx(k, q)]; yr = tt.x; yi =  tt.y; }
                    else       { float2 tt = u[uidx(q, k)]; yr = tt.x; yi = -tt.y; }
                    // nx = c*x + w*y ; ny = c*y - conj(w)*x
                    float nxr = c * xr + wr * yr - wi * yi;
                    float nxi = c * xi + wr * yi + wi * yr;
                    float nyr = c * yr - (wr * xr + wi * xi);
                    float nyi = c * yi - (wr * xi - wi * xr);
                    if (k < p) u[uidx(k, p)] = make_float2(nxr,  nxi);
                    else       u[uidx(p, k)] = make_float2(nxr, -nxi);
                    if (k < q) u[uidx(k, q)] = make_float2(nyr,  nyi);
                    else       u[uidx(q, k)] = make_float2(nyr, -nyi);
                }
            }
        }
    }

    // --- reduce (warp-uniform branch on mat) ---
    float l0 = 0.f, l7 = 0.f, sumS0 = 0.f, sumL0 = 0.f, sumS1 = 0.f, sumL1 = 0.f;
    if (mat == 0) {
#pragma unroll
        for (int i = 0; i < 7; ++i)
#pragma unroll
            for (int j = 0; j < 7 - i; ++j) {
                float lo = fminf(d8[j], d8[j + 1]);
                float hi = fmaxf(d8[j], d8[j + 1]);
                d8[j] = lo; d8[j + 1] = hi;
            }
        l0 = d8[0]; l7 = d8[7];
#pragma unroll
        for (int i = 0; i < 8; ++i) {
            if (i < n0)      sumS0 += d8[i];
            if (i >= 8 - n0) sumL0 += d8[i];
            if (i < n1)      sumS1 += d8[i];
            if (i >= 8 - n1) sumL1 += d8[i];
        }
    } else {
        float mn = d8[0], mx = d8[0];
#pragma unroll
        for (int i = 1; i < 8; ++i) { mn = fminf(mn, d8[i]); mx = fmaxf(mx, d8[i]); }
        ex[e][(mat - 1) * 2 + 0] = mn;
        ex[e][(mat - 1) * 2 + 1] = mx;
    }
    __syncthreads();

    if (mat == 0 && base + e < n) {
        float paMin = ex[e][0], paMax = ex[e][1];
        float pcMin = ex[e][2], pcMax = ex[e][3];

        const float beta0 = 1.f / (1.f - 8.f * (l0 + 0.125f));
        const float beta1 = 1.f / (1.f - 8.f * (l7 + 0.125f));

        float loss0 = beta0 * (beta0 >= 0.f ? sumS0 : sumL0) + (float)n0 * 0.125f;
        float loss1 = beta1 * (beta1 >= 0.f ? sumS1 : sumL1) + (float)n1 * 0.125f;
        float loss = (loss0 + loss1) * (loss0 + loss1);

        float lam;
        lam = beta0 * (beta0 >= 0.f ? paMin : paMax) + 0.125f; loss += lam * lam;
        lam = beta0 * (beta0 >= 0.f ? pcMin : pcMax) + 0.125f; loss += lam * lam;
        lam = beta1 * (beta1 >= 0.f ? paMin : paMax) + 0.125f; loss += lam * lam;
        lam = beta1 * (beta1 >= 0.f ? pcMin : pcMax) + 0.125f; loss += lam * lam;

        out[base + e] = loss;
    }
}

extern "C" void kernel_launch(void* const* d_in, const int* in_sizes, int n_in,
                              void* d_out, int out_size)
{
    const float* rho = (const float*)d_in[0];
    const int*   r0  = (const int*)d_in[1];
    const int*   r1  = (const int*)d_in[2];
    float* out = (float*)d_out;
    int n = in_sizes[0] / 63;
    int grid = (n + EPB - 1) / EPB;
    bes_kernel<<<grid, BLK>>>(rho, r0, r1, out, n);
}